// round 1
// baseline (speedup 1.0000x reference)
#include <cuda_runtime.h>
#include <cuda_bf16.h>

// Blur = UpFirDn2D(up=2, dn=2, k=4x4). Because the input is 2x zero-dilated
// and the conv strides by 2 with pad p0=1, only odd-index taps (1,3)x(1,3)
// ever align with real data. The whole op reduces to:
//   out[y][x] = f11*in[y][x] + f13*in[y][x+1] + f31*in[y+1][x] + f33*in[y+1][x+1]
// (zeros beyond the right/bottom edge). Pure HBM-bound 2x2 stencil.
//
// Shapes: x[8,256,128,128] f32, filt[256,1,4,4] f32, out[8,256,128,128] f32.

#define BB 8
#define CC 256
#define HH 128
#define WW 128

__global__ __launch_bounds__(256) void blur_kernel(
    const float* __restrict__ x,
    const float* __restrict__ filt,
    float* __restrict__ out)
{
    const int tid = blockIdx.x * blockDim.x + threadIdx.x;
    // 4 outputs per thread along W. W/4 = 32 quads per row.
    // tid layout: [b*C + c][y][xq]  ->  bits: xq=tid&31, y=(tid>>5)&127, bc=tid>>12
    const int xq = tid & 31;
    const int y  = (tid >> 5) & (HH - 1);
    const int bc = tid >> 12;           // b*256 + c, 0..2047
    const int c  = bc & (CC - 1);

    // Per-channel filter taps (same value across the block -> broadcast loads)
    const float* fp = filt + c * 16;
    const float w11 = fp[5];    // f[1][1]
    const float w13 = fp[7];    // f[1][3]
    const float w31 = fp[13];   // f[3][1]
    const float w33 = fp[15];   // f[3][3]

    const size_t base = ((size_t)bc << 14) + ((size_t)y << 7) + ((size_t)xq << 2);
    const float* row0 = x + base;

    float4 a = *(const float4*)row0;
    const bool lastx = (xq == 31);
    float a4 = lastx ? 0.0f : row0[4];

    float4 b;
    float b4;
    if (y < HH - 1) {
        b  = *(const float4*)(row0 + WW);
        b4 = lastx ? 0.0f : row0[WW + 4];
    } else {
        b  = make_float4(0.0f, 0.0f, 0.0f, 0.0f);
        b4 = 0.0f;
    }

    float4 o;
    o.x = w11 * a.x + w13 * a.y + w31 * b.x + w33 * b.y;
    o.y = w11 * a.y + w13 * a.z + w31 * b.y + w33 * b.z;
    o.z = w11 * a.z + w13 * a.w + w31 * b.z + w33 * b.w;
    o.w = w11 * a.w + w13 * a4  + w31 * b.w + w33 * b4;

    *(float4*)(out + base) = o;
}

extern "C" void kernel_launch(void* const* d_in, const int* in_sizes, int n_in,
                              void* d_out, int out_size)
{
    const float* x    = (const float*)d_in[0];
    const float* filt = (const float*)d_in[1];
    float* out        = (float*)d_out;

    // total threads = B*C*H*(W/4) = 8*256*128*32 = 2^23
    const int total_threads = BB * CC * HH * (WW / 4);
    const int block = 256;
    const int grid  = total_threads / block;   // 32768
    blur_kernel<<<grid, block>>>(x, filt, out);
}

// round 3
// speedup vs baseline: 1.1891x; 1.1891x over previous
#include <cuda_runtime.h>
#include <cuda_bf16.h>

// Blur = UpFirDn2D(up=2, dn=2, k=4x4) collapses to a 2x2 stencil:
//   out[y][x] = f11*in[y][x] + f13*in[y][x+1] + f31*in[y+1][x] + f33*in[y+1][x+1]
// (zeros past the right/bottom edge).
//
// R1 layout: warp = one full image row (32 lanes x float4 = 128 = W).
//  - +1-column neighbor comes from __shfl_down (lane31 == image edge -> 0),
//    eliminating the scalar edge LDGs.
//  - each thread produces R=4 output rows from R+1=5 loaded rows, cutting the
//    row re-read factor from 2.0x to 1.25x.
// L1 wavefronts per float4 output: 2.25 vs 5.0 in R0.

#define BB 8
#define CC 256
#define HH 128
#define WW 128
#define RR 4   // output rows per thread

__global__ __launch_bounds__(256) void blur_kernel(
    const float* __restrict__ x,
    const float* __restrict__ filt,
    float* __restrict__ out)
{
    const int lane    = threadIdx.x & 31;
    const int warp_id = blockIdx.x * (blockDim.x >> 5) + (threadIdx.x >> 5);
    // warp -> (bc, row-group). Row groups per channel image: H/R = 32.
    const int rg = warp_id & 31;
    const int bc = warp_id >> 5;          // b*C + c
    const int c  = bc & (CC - 1);
    const int y0 = rg << 2;               // first output row of this group

    // Per-channel taps: uniform across the warp -> broadcast loads.
    const float* fp = filt + c * 16;
    const float w11 = __ldg(fp + 5);
    const float w13 = __ldg(fp + 7);
    const float w31 = __ldg(fp + 13);
    const float w33 = __ldg(fp + 15);

    const size_t base = ((size_t)bc << 14) + ((size_t)y0 << 7) + ((size_t)lane << 2);
    const float* p = x + base;

    // Load R+1 = 5 input rows (front-batched for MLP).
    float4 r0 = *(const float4*)(p);
    float4 r1 = *(const float4*)(p + WW);
    float4 r2 = *(const float4*)(p + 2 * WW);
    float4 r3 = *(const float4*)(p + 3 * WW);
    float4 r4;
    if (rg < 31) {
        r4 = *(const float4*)(p + 4 * WW);
    } else {
        r4 = make_float4(0.0f, 0.0f, 0.0f, 0.0f);  // row 128 -> zero
    }

    // Next lane's .x = this thread's column x+4 neighbor. Lane 31 = image edge.
    float n0 = __shfl_down_sync(0xffffffffu, r0.x, 1);
    float n1 = __shfl_down_sync(0xffffffffu, r1.x, 1);
    float n2 = __shfl_down_sync(0xffffffffu, r2.x, 1);
    float n3 = __shfl_down_sync(0xffffffffu, r3.x, 1);
    float n4 = __shfl_down_sync(0xffffffffu, r4.x, 1);
    if (lane == 31) { n0 = n1 = n2 = n3 = n4 = 0.0f; }

    float* q = out + base;

    float4 o;
    // row 0: r0 (top), r1 (bottom)
    o.x = w11 * r0.x + w13 * r0.y + w31 * r1.x + w33 * r1.y;
    o.y = w11 * r0.y + w13 * r0.z + w31 * r1.y + w33 * r1.z;
    o.z = w11 * r0.z + w13 * r0.w + w31 * r1.z + w33 * r1.w;
    o.w = w11 * r0.w + w13 * n0   + w31 * r1.w + w33 * n1;
    *(float4*)(q) = o;

    // row 1
    o.x = w11 * r1.x + w13 * r1.y + w31 * r2.x + w33 * r2.y;
    o.y = w11 * r1.y + w13 * r1.z + w31 * r2.y + w33 * r2.z;
    o.z = w11 * r1.z + w13 * r1.w + w31 * r2.z + w33 * r2.w;
    o.w = w11 * r1.w + w13 * n1   + w31 * r2.w + w33 * n2;
    *(float4*)(q + WW) = o;

    // row 2
    o.x = w11 * r2.x + w13 * r2.y + w31 * r3.x + w33 * r3.y;
    o.y = w11 * r2.y + w13 * r2.z + w31 * r3.y + w33 * r3.z;
    o.z = w11 * r2.z + w13 * r2.w + w31 * r3.z + w33 * r3.w;
    o.w = w11 * r2.w + w13 * n2   + w31 * r3.w + w33 * n3;
    *(float4*)(q + 2 * WW) = o;

    // row 3
    o.x = w11 * r3.x + w13 * r3.y + w31 * r4.x + w33 * r4.y;
    o.y = w11 * r3.y + w13 * r3.z + w31 * r4.y + w33 * r4.z;
    o.z = w11 * r3.z + w13 * r3.w + w31 * r4.z + w33 * r4.w;
    o.w = w11 * r3.w + w13 * n3   + w31 * r4.w + w33 * n4;
    *(float4*)(q + 3 * WW) = o;
}

extern "C" void kernel_launch(void* const* d_in, const int* in_sizes, int n_in,
                              void* d_out, int out_size)
{
    const float* x    = (const float*)d_in[0];
    const float* filt = (const float*)d_in[1];
    float* out        = (float*)d_out;

    // warps = B*C*(H/R) = 2048*32 = 65536; 8 warps/block -> 8192 blocks
    const int block = 256;
    const int grid  = (BB * CC * (HH / RR) * 32) / block;
    blur_kernel<<<grid, block>>>(x, filt, out);
}